// round 13
// baseline (speedup 1.0000x reference)
#include <cuda_runtime.h>

// 4M-step sequential sigmoid recurrence via saturation-collapse chunking.
// Simple warp-autonomous shape (low regs), LCH=32, 13.2KB/warp -> 16 warps/SM.
// Persistent grid-stride over spans (1184 blocks = 8/SM exactly) to hold full
// residency through the whole kernel. Two launches total:
//   scan_warp  - all full spans
//   fixup      - flagged chunks (adaptive walk-back warmup, unconditionally
//                correct: degenerates to exact-from-net0) + uncovered tail.
// Sigmoid via single-MUFU tanh.approx: sig(10t) = 0.5*tanh(5t)+0.5.

#define LCH   32                 // steps per chunk (4 pieces of 8)
#define HWF   512                // fixup initial warmup
#define CHW   32                 // chunks per warp (one per lane)
#define WPB   2                  // warps per block
#define TPB   (WPB*32)
#define ROWB  400                // 384 data + 16 pad (stride/16 = 25, odd)
#define NROW  (CHW+1)            // 33 rows (row 0 = previous chunk)
#define SPANB (NROW*ROWB)        // 13200 B per warp
#define NF4   (NROW*24)          // 792 float4 per span (gmem-contiguous)
#define NCHMAX 131072
#define MAXBLK 1184              // 148 SMs x 8 blocks
#define C5    (5.0f)

__device__ unsigned char g_chunk_fail[NCHMAX];

__device__ __forceinline__ float tanha(float t){ float r; asm("tanh.approx.f32 %0, %1;" : "=f"(r) : "f"(t)); return r; }
// sigmoid(10*(n+u-0.5)) = 0.5*tanh(5n + v) + 0.5,  v = 5*(u-0.5)
__device__ __forceinline__ float sg(float n, float v){
    return fmaf(0.5f, tanha(fmaf(C5, n, v)), 0.5f);
}

#define MAKEV(x0,x1,x2) \
    float v0 = fmaf(cw00,(x0), fmaf(cw01,(x1), fmaf(cw02,(x2), cb0))); \
    float v1 = fmaf(cw10,(x0), fmaf(cw11,(x1), fmaf(cw12,(x2), cb1))); \
    float v2 = fmaf(cw20,(x0), fmaf(cw21,(x1), fmaf(cw22,(x2), cb2)));

#define LOADW \
    const float cb0 = C5*(__ldg(b+0)-0.5f), cb1 = C5*(__ldg(b+1)-0.5f), cb2 = C5*(__ldg(b+2)-0.5f); \
    const float cw00=C5*__ldg(W+0), cw01=C5*__ldg(W+1), cw02=C5*__ldg(W+2); \
    const float cw10=C5*__ldg(W+3), cw11=C5*__ldg(W+4), cw12=C5*__ldg(W+5); \
    const float cw20=C5*__ldg(W+6), cw21=C5*__ldg(W+7), cw22=C5*__ldg(W+8);

#define TWOSTEP(x0,x1,x2) do { \
    MAKEV(x0,x1,x2) \
    lo0=sg(lo0,v0); lo1=sg(lo1,v1); lo2=sg(lo2,v2); \
    hi0=sg(hi0,v0); hi1=sg(hi1,v1); hi2=sg(hi2,v2); } while(0)

#define ONESTEPW(x0,x1,x2) do { \
    MAKEV(x0,x1,x2) \
    lo0=sg(lo0,v0); lo1=sg(lo1,v1); lo2=sg(lo2,v2); } while(0)

#define MAINSTEP(x0,x1,x2,pd) do { \
    MAKEV(x0,x1,x2) \
    n0=sg(n0,v0); n1=sg(n1,v1); n2=sg(n2,v2); \
    pd = fmaf((x0),n0, fmaf((x1),n1, (x2)*n2)); } while(0)

#define BLOCK8(OP) do { \
    OP(c0.x,c0.y,c0.z,0); OP(c0.w,c1.x,c1.y,1); \
    OP(c1.z,c1.w,c2.x,2); OP(c2.y,c2.z,c2.w,3); \
    OP(c3.x,c3.y,c3.z,4); OP(c3.w,c4.x,c4.y,5); \
    OP(c4.z,c4.w,c5.x,6); OP(c5.y,c5.z,c5.w,7); } while(0)

#define OP_TWO(x0,x1,x2,j)  TWOSTEP(x0,x1,x2)
#define OP_ONE(x0,x1,x2,j)  ONESTEPW(x0,x1,x2)
#define OP_MAIN(x0,x1,x2,j) MAINSTEP(x0,x1,x2,p##j)

__global__ void __launch_bounds__(TPB)
scan_warp(const float* __restrict__ x, const float* __restrict__ W,
          const float* __restrict__ b, const float* __restrict__ net0,
          float* __restrict__ out, long nspan)
{
    extern __shared__ char smem_raw[];
    const int w    = threadIdx.x >> 5;
    const int lane = threadIdx.x & 31;
    const long warp0   = (long)blockIdx.x * WPB + w;
    const long wstride = (long)gridDim.x * WPB;
    char* sw = smem_raw + w * SPANB;
    unsigned sb;
    asm("{ .reg .u64 t; cvta.to.shared.u64 t, %1; cvt.u32.u64 %0, t; }" : "=r"(sb) : "l"(sw));

    LOADW

    for (long sp = warp0; sp < nspan; sp += wstride) {
        const long wc0 = sp * CHW;            // first chunk of this span

        // ---- stage span: chunks [wc0-1, wc0+32), 33 rows x 384B (contiguous) ----
        const char* gbase = (const char*)x + (wc0 - 1) * 384L;
        const bool e0 = (wc0 == 0);
        #pragma unroll
        for (int k = 0; k < (NF4 + 31) / 32; ++k) {
            int idx = k * 32 + lane;
            if (idx < NF4) {
                int r = idx / 24, o = idx - r * 24;
                unsigned dst = sb + r * ROWB + o * 16;
                const char* src = gbase + (long)idx * 16;
                int sz = 16;
                if (e0 && idx < 24) { src = (const char*)x; sz = 0; }   // zero row 0
                asm volatile("cp.async.cg.shared.global [%0], [%1], 16, %2;"
                             :: "r"(dst), "l"(src), "r"(sz));
            }
        }
        asm volatile("cp.async.commit_group;" ::: "memory");
        asm volatile("cp.async.wait_group 0;" ::: "memory");
        __syncwarp();

        // ---- warmup: lane t reads row t (= chunk c-1), 32 steps ----
        float lo0=0.f, lo1=0.f, lo2=0.f, hi0=1.f, hi1=1.f, hi2=1.f;
        const char* wrow = sw + lane * ROWB;
        bool col = false, ucol = false;
        #pragma unroll
        for (int p = 0; p < 4; ++p) {
            const float4* pc = (const float4*)(wrow + p * 96);
            float4 c0=pc[0], c1=pc[1], c2=pc[2], c3=pc[3], c4=pc[4], c5=pc[5];
            if (!ucol) {
                BLOCK8(OP_TWO);
                col  = (lo0==hi0) && (lo1==hi1) && (lo2==hi2);
                ucol = __all_sync(0xffffffffu, col);
            } else {
                BLOCK8(OP_ONE);
            }
        }
        float n0 = lo0, n1 = lo1, n2 = lo2;
        unsigned char fail = col ? 0 : 1;
        const long c = wc0 + lane;
        if (c == 0) { n0=__ldg(net0+0); n1=__ldg(net0+1); n2=__ldg(net0+2); fail = 0; }
        g_chunk_fail[c] = fail;
        __syncwarp();   // warmup reads done before preds overwrite rows

        // ---- main: lane t reads row t+1 (= chunk c); preds overwrite in place ----
        char* mrow = sw + (lane + 1) * ROWB;
        #pragma unroll
        for (int j = 0; j < 4; ++j) {
            const float4* pc = (const float4*)(mrow + j * 96);
            float4 c0=pc[0], c1=pc[1], c2=pc[2], c3=pc[3], c4=pc[4], c5=pc[5];
            float p0,p1,p2,p3,p4,p5,p6,p7;
            BLOCK8(OP_MAIN);
            float4* pw = (float4*)(mrow + j * 96);
            pw[0] = make_float4(p0,p1,p2,p3);
            pw[1] = make_float4(p4,p5,p6,p7);
        }
        __syncwarp();   // preds visible warp-wide before cross-lane gather

        // ---- coalesced output: 256 float4 = 32 chunks x 8 float4 ----
        float4* o4 = (float4*)out + wc0 * 8;
        #pragma unroll
        for (int k = 0; k < 8; ++k) {
            int f = k * 32 + lane;            // 0..255
            int cl  = f >> 3;                 // local chunk
            int rem = f & 7;                  // pred f4 within chunk
            const float4* srcv = (const float4*)(sw + (cl + 1) * ROWB
                                 + (rem >> 1) * 96 + (rem & 1) * 16);
            o4[f] = *srcv;
        }
        __syncwarp();   // gather done before next span restages this buffer
    }
}

// Fixup + tail, unconditionally correct. Processes:
//   - covered chunks whose interval bounds failed to collapse (adaptive
//     walk-back warmup: 512 steps, x4 each retry, up to exact start)
//   - all chunks beyond scan coverage (ncov..), incl. partial last chunk.
__global__ void fixup_kernel(const float* __restrict__ x, const float* __restrict__ W,
                             const float* __restrict__ b, const float* __restrict__ net0,
                             float* __restrict__ out, long ncovChunks, long nchAll, int nB)
{
    long cidx = (long)blockIdx.x * blockDim.x + threadIdx.x;
    if (cidx >= nchAll) return;
    if (cidx < ncovChunks && !g_chunk_fail[cidx]) return;
    long start = cidx * LCH;

    LOADW
    float n0, n1, n2;
    if (start == 0) {
        n0=__ldg(net0+0); n1=__ldg(net0+1); n2=__ldg(net0+2);
    } else {
        long hw = start < HWF ? start : HWF;
        bool col = false;
        for (;;) {
            const float* xp = x + 3*(start - hw);
            float lo0=0.f,lo1=0.f,lo2=0.f,hi0=1.f,hi1=1.f,hi2=1.f;
            col = false;
            for (long s = 0; s < hw; ++s) {
                float x0=xp[0], x1=xp[1], x2=xp[2]; xp += 3;
                MAKEV(x0,x1,x2)
                lo0=sg(lo0,v0); lo1=sg(lo1,v1); lo2=sg(lo2,v2);
                if (!col) {
                    hi0=sg(hi0,v0); hi1=sg(hi1,v1); hi2=sg(hi2,v2);
                    col = (lo0==hi0)&&(lo1==hi1)&&(lo2==hi2);
                }
            }
            if (hw == start) {       // reached sequence start: exact regardless
                // replay from net0 exactly
                const float* xq = x;
                float m0=__ldg(net0+0), m1=__ldg(net0+1), m2=__ldg(net0+2);
                for (long s = 0; s < start; ++s) {
                    float x0=xq[0], x1=xq[1], x2=xq[2]; xq += 3;
                    MAKEV(x0,x1,x2)
                    m0=sg(m0,v0); m1=sg(m1,v1); m2=sg(m2,v2);
                }
                lo0=m0; lo1=m1; lo2=m2; col = true;
            }
            if (col) { n0=lo0; n1=lo1; n2=lo2; break; }
            hw = (hw*4 < start) ? hw*4 : start;
        }
    }

    const float* xp = x + 3*start;
    long L = (start + LCH <= (long)nB) ? LCH : ((long)nB - start);
    for (long j = 0; j < L; ++j) {
        float x0=xp[0], x1=xp[1], x2=xp[2]; xp += 3;
        float pd; MAINSTEP(x0,x1,x2,pd);
        out[start + j] = pd;
    }
}

extern "C" void kernel_launch(void* const* d_in, const int* in_sizes, int n_in,
                              void* d_out, int out_size)
{
    const float *x = 0, *W = 0, *b = 0, *n0p = 0;
    long nB = out_size;
    for (int i = 0; i < n_in; ++i) {
        long sz = in_sizes[i];
        if (sz == 3 * nB)      x = (const float*)d_in[i];
        else if (sz == 9)      W = (const float*)d_in[i];
        else if (sz == 3) {
            if (!b) b = (const float*)d_in[i];
            else    n0p = (const float*)d_in[i];
        }
    }
    float* out = (float*)d_out;

    long nch   = nB / LCH;                 // full chunks (B=4M -> 131072)
    long nspan = nch / CHW;                // spans of 32 chunks (4096)
    long ncov  = nspan * CHW;              // chunks covered by scan_warp
    if (ncov > NCHMAX) { nspan = NCHMAX / CHW; ncov = nspan * CHW; }
    long nchAll = (nB + LCH - 1) / LCH;    // all chunks incl. partial tail

    long nblk = (nspan + WPB - 1) / WPB;
    if (nblk > MAXBLK) nblk = MAXBLK;      // persistent: 8 blocks/SM exactly

    size_t smem = (size_t)WPB * SPANB;     // 26400 B -> 8 blocks/SM, 16 warps/SM
    cudaFuncSetAttribute(scan_warp, cudaFuncAttributeMaxDynamicSharedMemorySize, (int)smem);

    if (nspan > 0)
        scan_warp<<<(int)nblk, TPB, smem>>>(x, W, b, n0p, out, nspan);
    if (nchAll > 0)
        fixup_kernel<<<(int)((nchAll + 255)/256), 256>>>(x, W, b, n0p, out,
                                                         ncov, nchAll, (int)nB);
}

// round 15
// speedup vs baseline: 1.1385x; 1.1385x over previous
#include <cuda_runtime.h>

// v2 resubmit (R14 infra failure; kernel unchanged).
// 4M-step sequential sigmoid recurrence via saturation-collapse chunking.
// Single persistent kernel: warp-autonomous spans (32 chunks, one per lane),
// LCH=32, 13.2KB/warp -> 16 warps/SM, grid-stride over spans.
// In-warp rescue: lanes whose interval bounds fail to collapse in the staged
// 32-step warmup redo warmup from gmem with growing depth (64->256->...->
// exact replay from net0), BEFORE the main phase -- so main always writes
// correct preds and the coalesced gather stores them once. Unconditionally
// correct with zero auxiliary launches (tail kernel only for non-divisible B).
// Sigmoid via single-MUFU tanh.approx: sig(10t) = 0.5*tanh(5t)+0.5.

#define LCH   32                 // steps per chunk (4 pieces of 8)
#define CHW   32                 // chunks per warp (one per lane)
#define WPB   2                  // warps per block
#define TPB   (WPB*32)
#define ROWB  400                // 384 data + 16 pad (stride/16 = 25, odd)
#define NROW  (CHW+1)            // 33 rows (row 0 = previous chunk)
#define SPANB (NROW*ROWB)        // 13200 B per warp
#define NF4   (NROW*24)          // 792 float4 per span (gmem-contiguous)
#define MAXBLK 1184              // 148 SMs x 8 blocks (smem-capped residency)
#define C5    (5.0f)

__device__ __forceinline__ float tanha(float t){ float r; asm("tanh.approx.f32 %0, %1;" : "=f"(r) : "f"(t)); return r; }
// sigmoid(10*(n+u-0.5)) = 0.5*tanh(5n + v) + 0.5,  v = 5*(u-0.5)
__device__ __forceinline__ float sg(float n, float v){
    return fmaf(0.5f, tanha(fmaf(C5, n, v)), 0.5f);
}

#define MAKEV(x0,x1,x2) \
    float v0 = fmaf(cw00,(x0), fmaf(cw01,(x1), fmaf(cw02,(x2), cb0))); \
    float v1 = fmaf(cw10,(x0), fmaf(cw11,(x1), fmaf(cw12,(x2), cb1))); \
    float v2 = fmaf(cw20,(x0), fmaf(cw21,(x1), fmaf(cw22,(x2), cb2)));

#define LOADW \
    const float cb0 = C5*(__ldg(b+0)-0.5f), cb1 = C5*(__ldg(b+1)-0.5f), cb2 = C5*(__ldg(b+2)-0.5f); \
    const float cw00=C5*__ldg(W+0), cw01=C5*__ldg(W+1), cw02=C5*__ldg(W+2); \
    const float cw10=C5*__ldg(W+3), cw11=C5*__ldg(W+4), cw12=C5*__ldg(W+5); \
    const float cw20=C5*__ldg(W+6), cw21=C5*__ldg(W+7), cw22=C5*__ldg(W+8);

#define TWOSTEP(x0,x1,x2) do { \
    MAKEV(x0,x1,x2) \
    lo0=sg(lo0,v0); lo1=sg(lo1,v1); lo2=sg(lo2,v2); \
    hi0=sg(hi0,v0); hi1=sg(hi1,v1); hi2=sg(hi2,v2); } while(0)

#define ONESTEPW(x0,x1,x2) do { \
    MAKEV(x0,x1,x2) \
    lo0=sg(lo0,v0); lo1=sg(lo1,v1); lo2=sg(lo2,v2); } while(0)

#define MAINSTEP(x0,x1,x2,pd) do { \
    MAKEV(x0,x1,x2) \
    n0=sg(n0,v0); n1=sg(n1,v1); n2=sg(n2,v2); \
    pd = fmaf((x0),n0, fmaf((x1),n1, (x2)*n2)); } while(0)

#define BLOCK8(OP) do { \
    OP(c0.x,c0.y,c0.z,0); OP(c0.w,c1.x,c1.y,1); \
    OP(c1.z,c1.w,c2.x,2); OP(c2.y,c2.z,c2.w,3); \
    OP(c3.x,c3.y,c3.z,4); OP(c3.w,c4.x,c4.y,5); \
    OP(c4.z,c4.w,c5.x,6); OP(c5.y,c5.z,c5.w,7); } while(0)

#define OP_TWO(x0,x1,x2,j)  TWOSTEP(x0,x1,x2)
#define OP_ONE(x0,x1,x2,j)  ONESTEPW(x0,x1,x2)
#define OP_MAIN(x0,x1,x2,j) MAINSTEP(x0,x1,x2,p##j)

// Gmem walk-back warmup used by the rare rescue path and the tail kernel.
// Returns exact (or interval-certified) state at step `start` in n0..n2.
__device__ __noinline__ void rescue_state(const float* __restrict__ x,
                                          const float* __restrict__ net0,
                                          long start,
                                          float cw00, float cw01, float cw02,
                                          float cw10, float cw11, float cw12,
                                          float cw20, float cw21, float cw22,
                                          float cb0, float cb1, float cb2,
                                          float& n0, float& n1, float& n2)
{
    long depth = 64;
    for (;;) {
        if (depth > start) depth = start;
        const float* xp = x + 3*(start - depth);
        float lo0=0.f,lo1=0.f,lo2=0.f,hi0=1.f,hi1=1.f,hi2=1.f;
        bool cc = false;
        for (long s = 0; s < depth; ++s) {
            float x0=xp[0], x1=xp[1], x2=xp[2]; xp += 3;
            MAKEV(x0,x1,x2)
            lo0=sg(lo0,v0); lo1=sg(lo1,v1); lo2=sg(lo2,v2);
            if (!cc) {
                hi0=sg(hi0,v0); hi1=sg(hi1,v1); hi2=sg(hi2,v2);
                cc = (lo0==hi0)&&(lo1==hi1)&&(lo2==hi2);
            }
        }
        if (cc) { n0=lo0; n1=lo1; n2=lo2; return; }
        if (depth == start) {            // exact replay from net0
            const float* xq = x;
            float m0=__ldg(net0+0), m1=__ldg(net0+1), m2=__ldg(net0+2);
            for (long s = 0; s < start; ++s) {
                float x0=xq[0], x1=xq[1], x2=xq[2]; xq += 3;
                MAKEV(x0,x1,x2)
                m0=sg(m0,v0); m1=sg(m1,v1); m2=sg(m2,v2);
            }
            n0=m0; n1=m1; n2=m2; return;
        }
        depth *= 4;
    }
}

__global__ void __launch_bounds__(TPB)
scan_warp(const float* __restrict__ x, const float* __restrict__ W,
          const float* __restrict__ b, const float* __restrict__ net0,
          float* __restrict__ out, long nspan)
{
    extern __shared__ char smem_raw[];
    const int w    = threadIdx.x >> 5;
    const int lane = threadIdx.x & 31;
    const long warp0   = (long)blockIdx.x * WPB + w;
    const long wstride = (long)gridDim.x * WPB;
    char* sw = smem_raw + w * SPANB;
    unsigned sb;
    asm("{ .reg .u64 t; cvta.to.shared.u64 t, %1; cvt.u32.u64 %0, t; }" : "=r"(sb) : "l"(sw));

    LOADW

    for (long sp = warp0; sp < nspan; sp += wstride) {
        const long wc0 = sp * CHW;            // first chunk of this span

        // ---- stage span: chunks [wc0-1, wc0+32), 33 rows x 384B (contiguous) ----
        const char* gbase = (const char*)x + (wc0 - 1) * 384L;
        const bool e0 = (wc0 == 0);
        #pragma unroll
        for (int k = 0; k < (NF4 + 31) / 32; ++k) {
            int idx = k * 32 + lane;
            if (idx < NF4) {
                int r = idx / 24, o = idx - r * 24;
                unsigned dst = sb + r * ROWB + o * 16;
                const char* src = gbase + (long)idx * 16;
                int sz = 16;
                if (e0 && idx < 24) { src = (const char*)x; sz = 0; }   // zero row 0
                asm volatile("cp.async.cg.shared.global [%0], [%1], 16, %2;"
                             :: "r"(dst), "l"(src), "r"(sz));
            }
        }
        asm volatile("cp.async.commit_group;" ::: "memory");
        asm volatile("cp.async.wait_group 0;" ::: "memory");
        __syncwarp();

        // ---- warmup: lane t reads row t (= chunk c-1), 32 steps ----
        float lo0=0.f, lo1=0.f, lo2=0.f, hi0=1.f, hi1=1.f, hi2=1.f;
        const char* wrow = sw + lane * ROWB;
        bool col = false, ucol = false;
        #pragma unroll
        for (int p = 0; p < 4; ++p) {
            const float4* pc = (const float4*)(wrow + p * 96);
            float4 c0=pc[0], c1=pc[1], c2=pc[2], c3=pc[3], c4=pc[4], c5=pc[5];
            if (!ucol) {
                BLOCK8(OP_TWO);
                col  = (lo0==hi0) && (lo1==hi1) && (lo2==hi2);
                ucol = __all_sync(0xffffffffu, col);
            } else {
                BLOCK8(OP_ONE);
            }
        }
        float n0 = lo0, n1 = lo1, n2 = lo2;
        const long c = wc0 + lane;
        if (c == 0) { n0=__ldg(net0+0); n1=__ldg(net0+1); n2=__ldg(net0+2); }

        // ---- rare rescue: uncollapsed lanes re-derive state from gmem ----
        bool fail = (!col) && (c != 0);
        if (__any_sync(0xffffffffu, fail)) {
            if (fail) {
                rescue_state(x, net0, c * (long)LCH,
                             cw00,cw01,cw02, cw10,cw11,cw12, cw20,cw21,cw22,
                             cb0,cb1,cb2, n0,n1,n2);
            }
            __syncwarp();
        }
        __syncwarp();   // warmup reads done before preds overwrite rows

        // ---- main: lane t reads row t+1 (= chunk c); preds overwrite in place ----
        char* mrow = sw + (lane + 1) * ROWB;
        #pragma unroll
        for (int j = 0; j < 4; ++j) {
            const float4* pc = (const float4*)(mrow + j * 96);
            float4 c0=pc[0], c1=pc[1], c2=pc[2], c3=pc[3], c4=pc[4], c5=pc[5];
            float p0,p1,p2,p3,p4,p5,p6,p7;
            BLOCK8(OP_MAIN);
            float4* pw = (float4*)(mrow + j * 96);
            pw[0] = make_float4(p0,p1,p2,p3);
            pw[1] = make_float4(p4,p5,p6,p7);
        }
        __syncwarp();   // preds visible warp-wide before cross-lane gather

        // ---- coalesced output: 256 float4 = 32 chunks x 8 float4 ----
        float4* o4 = (float4*)out + wc0 * 8;
        #pragma unroll
        for (int k = 0; k < 8; ++k) {
            int f = k * 32 + lane;            // 0..255
            int cl  = f >> 3;                 // local chunk
            int rem = f & 7;                  // pred f4 within chunk
            const float4* srcv = (const float4*)(sw + (cl + 1) * ROWB
                                 + (rem >> 1) * 96 + (rem & 1) * 16);
            o4[f] = *srcv;
        }
        __syncwarp();   // gather done before next span restages this buffer
    }
}

// Tail: chunks beyond span coverage (launched only when B isn't divisible).
__global__ void tail_kernel(const float* __restrict__ x, const float* __restrict__ W,
                            const float* __restrict__ b, const float* __restrict__ net0,
                            float* __restrict__ out, long firstStep, int nB)
{
    long idx = (long)blockIdx.x * blockDim.x + threadIdx.x;
    long start = firstStep + idx * LCH;
    if (start >= (long)nB) return;

    LOADW
    float n0, n1, n2;
    if (start == 0) { n0=__ldg(net0+0); n1=__ldg(net0+1); n2=__ldg(net0+2); }
    else rescue_state(x, net0, start,
                      cw00,cw01,cw02, cw10,cw11,cw12, cw20,cw21,cw22,
                      cb0,cb1,cb2, n0,n1,n2);

    const float* xp = x + 3*start;
    long L = (start + LCH <= (long)nB) ? LCH : ((long)nB - start);
    for (long j = 0; j < L; ++j) {
        float x0=xp[0], x1=xp[1], x2=xp[2]; xp += 3;
        float pd; MAINSTEP(x0,x1,x2,pd);
        out[start + j] = pd;
    }
}

extern "C" void kernel_launch(void* const* d_in, const int* in_sizes, int n_in,
                              void* d_out, int out_size)
{
    const float *x = 0, *W = 0, *b = 0, *n0p = 0;
    long nB = out_size;
    for (int i = 0; i < n_in; ++i) {
        long sz = in_sizes[i];
        if (sz == 3 * nB)      x = (const float*)d_in[i];
        else if (sz == 9)      W = (const float*)d_in[i];
        else if (sz == 3) {
            if (!b) b = (const float*)d_in[i];
            else    n0p = (const float*)d_in[i];
        }
    }
    float* out = (float*)d_out;

    long nch   = nB / LCH;                 // full chunks (B=4M -> 131072)
    long nspan = nch / CHW;                // spans of 32 chunks (4096)
    long firstEdge = nspan * CHW * LCH;    // == nB for B=4M

    long nblk = (nspan + WPB - 1) / WPB;
    if (nblk > MAXBLK) nblk = MAXBLK;      // persistent: 8 blocks/SM

    size_t smem = (size_t)WPB * SPANB;     // 26400 B -> 8 blocks/SM, 16 warps/SM
    cudaFuncSetAttribute(scan_warp, cudaFuncAttributeMaxDynamicSharedMemorySize, (int)smem);

    if (nspan > 0)
        scan_warp<<<(int)nblk, TPB, smem>>>(x, W, b, n0p, out, nspan);
    if (firstEdge < nB) {
        long nTail = (nB - firstEdge + LCH - 1) / LCH;
        tail_kernel<<<(int)((nTail + 127)/128), 128>>>(x, W, b, n0p, out, firstEdge, (int)nB);
    }
}